// round 4
// baseline (speedup 1.0000x reference)
#include <cuda_runtime.h>
#include <math.h>

#define TPB 128
#define NS 4

typedef unsigned long long ull;

__device__ __forceinline__ ull pk2(float lo, float hi) {
    ull r; asm("mov.b64 %0, {%1,%2};" : "=l"(r) : "f"(lo), "f"(hi)); return r;
}
__device__ __forceinline__ float2 unpk2(ull v) {
    float2 f; asm("mov.b64 {%0,%1}, %2;" : "=f"(f.x), "=f"(f.y) : "l"(v)); return f;
}
__device__ __forceinline__ ull mul2(ull a, ull b) {
    ull r; asm("mul.rn.f32x2 %0, %1, %2;" : "=l"(r) : "l"(a), "l"(b)); return r;
}
__device__ __forceinline__ ull fma2(ull a, ull b, ull c) {
    ull r; asm("fma.rn.f32x2 %0, %1, %2, %3;" : "=l"(r) : "l"(a), "l"(b), "l"(c)); return r;
}
__device__ __forceinline__ ull add2(ull a, ull b) {
    ull r; asm("add.rn.f32x2 %0, %1, %2;" : "=l"(r) : "l"(a), "l"(b)); return r;
}

__global__ __launch_bounds__(TPB) void pmsn_kernel(
    const float* __restrict__ log_dt,
    const float* __restrict__ log_A_real,
    const float* __restrict__ A_imag,
    const float* __restrict__ VinvB_real,
    const float* __restrict__ VinvB_imag,
    const float* __restrict__ CV_real,
    const float* __restrict__ CV_imag,
    float* __restrict__ out, int L)
{
    const int warp = threadIdx.x >> 5;
    const int lane = threadIdx.x & 31;
    const int h = blockIdx.x * (TPB / 32) + warp;

    const double TWO_PI     = 6.283185307179586476925286766559;
    const double INV_TWO_PI = 0.15915494309189533576888376337251;

    const float dt = expf(log_dt[h]);

    // A*dt per state (all lanes)
    float adr[NS], adi[NS];
#pragma unroll
    for (int n = 0; n < NS; ++n) {
        const int idx = h * NS + n;
        const float Are = -expf(log_A_real[idx]);
        adr[n] = Are * dt;
        adi[n] = A_imag[idx] * dt;
    }

    // Special lanes: lane 2n -> A_bar=exp(Adt) (+ rotators + coef), lane 2n+1 -> R=A_bar^128
    const int sp_n = lane >> 1;
    float sp_re = 0.f, sp_im = 0.f;
    float a2re = 0.f, a2im = 0.f, a3re = 0.f, a3im = 0.f, cfre = 0.f, cfim = 0.f;
    if (lane < 2 * NS) {
        const int   spR = lane & 1;
        const float ar = adr[sp_n], ai = adi[sp_n];
        const float e  = spR ? 128.0f : 1.0f;
        double ph = (double)ai * (double)e;
        ph -= floor(ph * INV_TWO_PI) * TWO_PI;
        float s, c;
        sincosf((float)ph, &s, &c);
        const float m = expf(ar * e);
        sp_re = m * c; sp_im = m * s;
        if (!spR) {
            // rotators A_bar^2, A_bar^3
            a2re = sp_re * sp_re - sp_im * sp_im;
            a2im = 2.f * sp_re * sp_im;
            a3re = a2re * sp_re - a2im * sp_im;
            a3im = a2re * sp_im + a2im * sp_re;
            // coef = C * (A_bar-1)/A * B
            const int idx = h * NS + sp_n;
            const float Are = -expf(log_A_real[idx]);
            const float Aim = A_imag[idx];
            const float inv = 1.f / (Are * Are + Aim * Aim);
            const float iAr =  Are * inv, iAi = -Aim * inv;
            const float mr = sp_re - 1.f, mi = sp_im;
            const float qr = mr * iAr - mi * iAi;
            const float qi = mr * iAi + mi * iAr;
            const float Br = VinvB_real[idx], Bi = VinvB_imag[idx];
            const float bbr = qr * Br - qi * Bi;
            const float bbi = qr * Bi + qi * Br;
            const float Cr = CV_real[idx], Ci = CV_imag[idx];
            cfre = Cr * bbr - Ci * bbi;
            cfim = Cr * bbi + Ci * bbr;
        }
    }

    // Per-lane start + packed phase-pair state
    ull xp01[NS], xp23[NS], xc01[NS], xc23[NS], p2[NS], q2[NS];
    const float e4 = (float)(4 * lane);
#pragma unroll
    for (int n = 0; n < NS; ++n) {
        // w = exp(Adt * 4*lane), phase reduced in double
        double ph = (double)adi[n] * (double)(4 * lane);
        ph -= floor(ph * INV_TWO_PI) * TWO_PI;
        float s, c;
        sincosf((float)ph, &s, &c);
        const float m = expf(adr[n] * e4);
        const float wre = m * c, wim = m * s;

        const float c1  = __shfl_sync(0xffffffffu, sp_re, 2 * n);
        const float s1  = __shfl_sync(0xffffffffu, sp_im, 2 * n);
        const float Rre = __shfl_sync(0xffffffffu, sp_re, 2 * n + 1);
        const float Rim = __shfl_sync(0xffffffffu, sp_im, 2 * n + 1);
        const float c2  = __shfl_sync(0xffffffffu, a2re, 2 * n);
        const float s2  = __shfl_sync(0xffffffffu, a2im, 2 * n);
        const float c3  = __shfl_sync(0xffffffffu, a3re, 2 * n);
        const float s3  = __shfl_sync(0xffffffffu, a3im, 2 * n);
        const float kr  = __shfl_sync(0xffffffffu, cfre, 2 * n);
        const float ki  = __shfl_sync(0xffffffffu, cfim, 2 * n);

        // v = coef * w  (j=0 state), u = v * R  (j=1 state)
        const float vre = kr * wre - ki * wim;
        const float vim = kr * wim + ki * wre;
        const float ure = vre * Rre - vim * Rim;
        const float uim = vre * Rim + vim * Rre;

        xp01[n] = pk2(vre,                vre * c1 - vim * s1);
        xp23[n] = pk2(vre * c2 - vim * s2, vre * c3 - vim * s3);
        xc01[n] = pk2(ure,                ure * c1 - uim * s1);
        xc23[n] = pk2(ure * c2 - uim * s2, ure * c3 - uim * s3);

        const float pp = Rre + Rre;
        const float qq = -(Rre * Rre + Rim * Rim);
        p2[n] = pk2(pp, pp);
        q2[n] = pk2(qq, qq);
    }

    float* __restrict__ orow = out + (size_t)h * (size_t)L + 4 * lane;
    const int NJ = L >> 7;     // L / 128

    // j = 0, 1 from the initialized history
    if (NJ > 0) {
        const ull a01 = add2(add2(xp01[0], xp01[1]), add2(xp01[2], xp01[3]));
        const ull a23 = add2(add2(xp23[0], xp23[1]), add2(xp23[2], xp23[3]));
        const float2 a = unpk2(a01), b = unpk2(a23);
        *(float4*)orow = make_float4(a.x, a.y, b.x, b.y);
    }
    if (NJ > 1) {
        const ull a01 = add2(add2(xc01[0], xc01[1]), add2(xc01[2], xc01[3]));
        const ull a23 = add2(add2(xc23[0], xc23[1]), add2(xc23[2], xc23[3]));
        const float2 a = unpk2(a01), b = unpk2(a23);
        *(float4*)(orow + 128) = make_float4(a.x, a.y, b.x, b.y);
    }

    // main recurrence: x_j = p*x_{j-1} + q*x_{j-2} per state; emit packed sums
#pragma unroll 6
    for (int j = 2; j < NJ; ++j) {
#pragma unroll
        for (int n = 0; n < NS; ++n) {
            const ull t01 = fma2(p2[n], xc01[n], mul2(q2[n], xp01[n]));
            xp01[n] = xc01[n]; xc01[n] = t01;
            const ull t23 = fma2(p2[n], xc23[n], mul2(q2[n], xp23[n]));
            xp23[n] = xc23[n]; xc23[n] = t23;
        }
        const ull a01 = add2(add2(xc01[0], xc01[1]), add2(xc01[2], xc01[3]));
        const ull a23 = add2(add2(xc23[0], xc23[1]), add2(xc23[2], xc23[3]));
        const float2 a = unpk2(a01), b = unpk2(a23);
        *(float4*)(orow + (size_t)j * 128) = make_float4(a.x, a.y, b.x, b.y);
    }
}

extern "C" void kernel_launch(void* const* d_in, const int* in_sizes, int n_in,
                              void* d_out, int out_size) {
    const float* log_dt     = (const float*)d_in[0];
    const float* log_A_real = (const float*)d_in[1];
    const float* A_imag     = (const float*)d_in[2];
    const float* VinvB_real = (const float*)d_in[3];
    const float* VinvB_imag = (const float*)d_in[4];
    const float* CV_real    = (const float*)d_in[5];
    const float* CV_imag    = (const float*)d_in[6];
    const int H = in_sizes[0];               // 2048
    const int L = out_size / H;              // 4096
    pmsn_kernel<<<H / (TPB / 32), TPB>>>(log_dt, log_A_real, A_imag,
                                         VinvB_real, VinvB_imag,
                                         CV_real, CV_imag, (float*)d_out, L);
}